// round 11
// baseline (speedup 1.0000x reference)
#include <cuda_runtime.h>
#include <cuda_bf16.h>

// Problem shape (fixed by the dataset): image (2048, 8192, 4) fp32 -> points (2048*8192, 3) fp32
#define H 2048
#define W 8192
#define NPIX (H * W)
#define PIX_PER_THREAD 8
#define NTHREADS (NPIX / PIX_PER_THREAD)   // 2,097,152
#define BLOCK 256

// ---------------------------------------------------------------------------
// Compile-time trig tables: 12-term Taylor in double (|err| < 2e-13 on [-pi,pi]).
// NON-const __device__ global (constexpr initializer only) -> .global placement.
// (R9 showed a const/constexpr table is routed through the constant-bank/LDC
// path whose half-rate divergent-address port throttled the kernel to 106 us.)
// ---------------------------------------------------------------------------
constexpr double PI_D = 3.141592653589793238462643383279502884;

constexpr double tsin(double x) {
    double x2 = x * x, term = x, sum = x;
    for (int k = 1; k <= 12; ++k) {
        term *= -x2 / (double)((2 * k) * (2 * k + 1));
        sum += term;
    }
    return sum;
}
constexpr double tcos(double x) {
    double x2 = x * x, term = 1.0, sum = 1.0;
    for (int k = 1; k <= 12; ++k) {
        term *= -x2 / (double)((2 * k - 1) * (2 * k));
        sum += term;
    }
    return sum;
}

struct alignas(16) Tables {
    float cy[W];   // cos(yaw_j)
    float sy[W];   // -sin(yaw_j)  (minus folded in)
    float sp[H];   // sin(pitch_i)
};

constexpr Tables make_tables() {
    Tables t{};
    const double FOV_DOWN_ABS = 15.0 / 180.0 * PI_D;
    const double FOV_SPAN     = 30.0 / 180.0 * PI_D;
    for (int j = 0; j < W; ++j) {
        double yaw = (double)j / (double)W * (2.0 * PI_D) - PI_D;
        t.cy[j] = (float)tcos(yaw);
        t.sy[j] = (float)(-tsin(yaw));
    }
    for (int i = 0; i < H; ++i) {
        double pitch = (1.0 - (double)i / (double)H) * FOV_SPAN - FOV_DOWN_ABS;
        t.sp[i] = (float)tsin(pitch);
    }
    return t;
}

__device__ Tables g_tab = make_tables();

// ---------------------------------------------------------------------------
// Main streaming kernel: 8 consecutive pixels per thread.
// 8 front-batched LDG.128 (MLP_p1=8), 2 table float4 loads, 6 dense STG.128.
// ---------------------------------------------------------------------------
__global__ void __launch_bounds__(BLOCK)
project_kernel(const float4* __restrict__ im, float4* __restrict__ out) {
    int t  = blockIdx.x * BLOCK + threadIdx.x;     // 0 .. NTHREADS-1
    int p0 = t << 3;                               // first pixel (8 per thread)
    int row = p0 >> 13;                            // / W  (W = 8192)
    int c4  = (t << 1) & 2047;                     // float4 index into column tables

    float sp = g_tab.sp[row];
    const float4* __restrict__ cy4 = reinterpret_cast<const float4*>(g_tab.cy);
    const float4* __restrict__ sy4 = reinterpret_cast<const float4*>(g_tab.sy);
    float4 cyA = __ldg(cy4 + c4);
    float4 cyB = __ldg(cy4 + c4 + 1);
    float4 syA = __ldg(sy4 + c4);
    float4 syB = __ldg(sy4 + c4 + 1);

    // 8 consecutive pixels, depth is the .w channel (independent loads -> deep MLP)
    float4 v0 = im[p0 + 0];
    float4 v1 = im[p0 + 1];
    float4 v2 = im[p0 + 2];
    float4 v3 = im[p0 + 3];
    float4 v4 = im[p0 + 4];
    float4 v5 = im[p0 + 5];
    float4 v6 = im[p0 + 6];
    float4 v7 = im[p0 + 7];

    float d0 = v0.w, d1 = v1.w, d2 = v2.w, d3 = v3.w;
    float d4 = v4.w, d5 = v5.w, d6 = v6.w, d7 = v7.w;

    float x0 = d0 * cyA.x, y0 = d0 * syA.x, z0 = d0 * sp;
    float x1 = d1 * cyA.y, y1 = d1 * syA.y, z1 = d1 * sp;
    float x2 = d2 * cyA.z, y2 = d2 * syA.z, z2 = d2 * sp;
    float x3 = d3 * cyA.w, y3 = d3 * syA.w, z3 = d3 * sp;
    float x4 = d4 * cyB.x, y4 = d4 * syB.x, z4 = d4 * sp;
    float x5 = d5 * cyB.y, y5 = d5 * syB.y, z5 = d5 * sp;
    float x6 = d6 * cyB.z, y6 = d6 * syB.z, z6 = d6 * sp;
    float x7 = d7 * cyB.w, y7 = d7 * syB.w, z7 = d7 * sp;

    // 24 contiguous output floats -> 6 dense float4 stores
    int ob = 6 * t;
    out[ob + 0] = make_float4(x0, y0, z0, x1);
    out[ob + 1] = make_float4(y1, z1, x2, y2);
    out[ob + 2] = make_float4(z2, x3, y3, z3);
    out[ob + 3] = make_float4(x4, y4, z4, x5);
    out[ob + 4] = make_float4(y5, z5, x6, y6);
    out[ob + 5] = make_float4(z6, x7, y7, z7);
}

extern "C" void kernel_launch(void* const* d_in, const int* in_sizes, int n_in,
                              void* d_out, int out_size) {
    (void)in_sizes; (void)n_in; (void)out_size;
    const float4* im = (const float4*)d_in[0];
    float4* out = (float4*)d_out;

    // Single-node graph: tables baked into the module's .global image.
    project_kernel<<<NTHREADS / BLOCK, BLOCK>>>(im, out);
}

// round 13
// speedup vs baseline: 1.3986x; 1.3986x over previous
#include <cuda_runtime.h>
#include <cuda_bf16.h>

// Problem shape (fixed by the dataset): image (2048, 8192, 4) fp32 -> points (2048*8192, 3) fp32
#define H 2048
#define W 8192
#define NPIX (H * W)
#define BLOCK 256
#define PX_PER_BLOCK 512                    // 2 pixels per thread, block never crosses a row
#define NBLOCKS (NPIX / PX_PER_BLOCK)       // 32768

// ---------------------------------------------------------------------------
// Compile-time trig tables: 12-term Taylor in double (|err| < 2e-13 on [-pi,pi]).
// NON-const __device__ global (constexpr initializer only) -> .global placement.
// (R9 showed a const/constexpr table is routed through the constant-bank/LDC
// path whose half-rate divergent-address port throttled the kernel to 106 us.)
// ---------------------------------------------------------------------------
constexpr double PI_D = 3.141592653589793238462643383279502884;

constexpr double tsin(double x) {
    double x2 = x * x, term = x, sum = x;
    for (int k = 1; k <= 12; ++k) {
        term *= -x2 / (double)((2 * k) * (2 * k + 1));
        sum += term;
    }
    return sum;
}
constexpr double tcos(double x) {
    double x2 = x * x, term = 1.0, sum = 1.0;
    for (int k = 1; k <= 12; ++k) {
        term *= -x2 / (double)((2 * k - 1) * (2 * k));
        sum += term;
    }
    return sum;
}

struct alignas(16) Tables {
    float cy[W];   // cos(yaw_j)
    float sy[W];   // -sin(yaw_j)  (minus folded in)
    float sp[H];   // sin(pitch_i)
};

constexpr Tables make_tables() {
    Tables t{};
    const double FOV_DOWN_ABS = 15.0 / 180.0 * PI_D;
    const double FOV_SPAN     = 30.0 / 180.0 * PI_D;
    for (int j = 0; j < W; ++j) {
        double yaw = (double)j / (double)W * (2.0 * PI_D) - PI_D;
        t.cy[j] = (float)tcos(yaw);
        t.sy[j] = (float)(-tsin(yaw));
    }
    for (int i = 0; i < H; ++i) {
        double pitch = (1.0 - (double)i / (double)H) * FOV_SPAN - FOV_DOWN_ABS;
        t.sp[i] = (float)tsin(pitch);
    }
    return t;
}

__device__ Tables g_tab = make_tables();

// ---------------------------------------------------------------------------
// Fully-coalesced streaming kernel: 1x L1 wavefront amplification on BOTH
// loads (warp-contiguous LDG.128) and stores (smem repack -> dense STG.128).
// ---------------------------------------------------------------------------
__global__ void __launch_bounds__(BLOCK)
project_kernel(const float4* __restrict__ im, float4* __restrict__ out) {
    __shared__ float s[PX_PER_BLOCK * 3];   // 6144 B: xyz in final output order

    const int b    = blockIdx.x;
    const int tid  = threadIdx.x;
    const int pix0 = b * PX_PER_BLOCK;      // first pixel of this block
    const int row  = pix0 >> 13;            // / W ; whole block lies in one row
    const int col0 = pix0 & (W - 1);        // first column of this block

    const float sp = g_tab.sp[row];

    // Warp-contiguous pixel loads (512B per LDG.128 warp-wide = 4 wavefronts, minimum)
    float4 v0 = im[pix0 + tid];
    float4 v1 = im[pix0 + BLOCK + tid];

    // Coalesced scalar table loads (1 line per warp per load)
    float cy0 = __ldg(&g_tab.cy[col0 + tid]);
    float sy0 = __ldg(&g_tab.sy[col0 + tid]);
    float cy1 = __ldg(&g_tab.cy[col0 + BLOCK + tid]);
    float sy1 = __ldg(&g_tab.sy[col0 + BLOCK + tid]);

    // Compute and scatter into smem in output order.
    // STS word addresses 3t+c: 3t mod 32 is a permutation (gcd(3,32)=1) -> conflict-free.
    float d0 = v0.w, d1 = v1.w;
    int l0 = 3 * tid;
    s[l0 + 0] = d0 * cy0;
    s[l0 + 1] = d0 * sy0;
    s[l0 + 2] = d0 * sp;
    int l1 = 3 * (tid + BLOCK);
    s[l1 + 0] = d1 * cy1;
    s[l1 + 1] = d1 * sy1;
    s[l1 + 2] = d1 * sp;

    __syncthreads();

    // Dense, warp-contiguous float4 stores: 384 float4s per block, 1x amplification.
    const float4* s4 = reinterpret_cast<const float4*>(s);
    float4* ob = out + (size_t)b * (PX_PER_BLOCK * 3 / 4);   // 384 float4s per block
    ob[tid] = s4[tid];
    if (tid < PX_PER_BLOCK * 3 / 4 - BLOCK)                  // 128 remaining
        ob[BLOCK + tid] = s4[BLOCK + tid];
}

extern "C" void kernel_launch(void* const* d_in, const int* in_sizes, int n_in,
                              void* d_out, int out_size) {
    (void)in_sizes; (void)n_in; (void)out_size;
    const float4* im = (const float4*)d_in[0];
    float4* out = (float4*)d_out;

    // Single-node graph: tables baked into the module's .global image.
    project_kernel<<<NBLOCKS, BLOCK>>>(im, out);
}